// round 4
// baseline (speedup 1.0000x reference)
#include <cuda_runtime.h>
#include <cstdint>

// ---------------------------------------------------------------------------
// HierarchUpdateMlp — tf32 mma.sync, 3-stage ring, single barrier per stage
//   L1:  out1[:,g] = relu(gather_g(update) @ W1g^T + b1g)   g=0..6
//   L2:  out2[:,g] = relu(gather_g(out1)   @ W2g^T + b2g)   g=0..5
//   L3:  out       = relu(out2 @ Wf^T + bf)
// Weights in [out,in] row-major are already the n-major B layout we need.
// ---------------------------------------------------------------------------

#define NROWS_MAX 50176   // 392 tiles of 128 (N = 50000)

__device__ __align__(16) float g_W1_0[128 * 1280];
__device__ __align__(16) float g_W1[6 * 128 * 512];
__device__ __align__(16) float g_W2[6 * 128 * 256];
__device__ __align__(16) float g_Wf[256 * 768];
__device__ __align__(16) float g_out1[(size_t)NROWS_MAX * 896];
__device__ __align__(16) float g_out2[(size_t)NROWS_MAX * 768];

__constant__ int c_jA[7] = {0, 5, 7, 8, 11, 13, 14};
__constant__ int c_jB[7] = {0, 6, 9, 10, 12, 15, 16};
__constant__ int c_pA[6] = {0, 1, 1, 1, 4, 4};
__constant__ int c_pB[6] = {1, 2, 3, 4, 5, 6};

#define STAGES 3
#define STAGE_FLOATS 8192            // A 128x32 + B 128x32 floats (32 KB)
#define SMEM_TOTAL (STAGES * STAGE_FLOATS * 4)

__device__ __forceinline__ float tf32_round(float x) {
    unsigned u;
    asm("cvt.rna.tf32.f32 %0, %1;" : "=r"(u) : "f"(x));
    return __uint_as_float(u);
}

__device__ __forceinline__ unsigned smem_u32(const void* p) {
    return (unsigned)__cvta_generic_to_shared(p);
}

__device__ __forceinline__ void ldsm4(unsigned addr, unsigned& r0, unsigned& r1,
                                      unsigned& r2, unsigned& r3) {
    asm volatile("ldmatrix.sync.aligned.m8n8.x4.shared.b16 {%0,%1,%2,%3}, [%4];"
                 : "=r"(r0), "=r"(r1), "=r"(r2), "=r"(r3)
                 : "r"(addr));
}

__device__ __forceinline__ void mma_tf32(float* c, const unsigned* a, const unsigned* b) {
    asm volatile(
        "mma.sync.aligned.m16n8k8.row.col.f32.tf32.tf32.f32 "
        "{%0,%1,%2,%3}, {%4,%5,%6,%7}, {%8,%9}, {%0,%1,%2,%3};"
        : "+f"(c[0]), "+f"(c[1]), "+f"(c[2]), "+f"(c[3])
        : "r"(a[0]), "r"(a[1]), "r"(a[2]), "r"(a[3]), "r"(b[0]), "r"(b[1]));
}

// Generic 128(M) x 128(N) tile GEMM. A gathered from up to 2 contiguous blocks:
//   col(k) = (k < blk) ? offA0 + k : offA1 + (k - blk)
// B is n-major [128][K] (weight row-major [out][in]). K multiple of 32.
template <bool ROUND_OUT>
__device__ __forceinline__ void gemm_core(
    const float* __restrict__ A, int lda, int offA0, int offA1, int blk,
    const float* __restrict__ B, int ldb,
    const float* __restrict__ bias,
    float* __restrict__ C, int ldc,
    int K, int nrows)
{
    extern __shared__ float sm[];   // STAGES x [A 128x32 | B 128x32]
    const int tid   = threadIdx.x;
    const int lane  = tid & 31;
    const int wid   = tid >> 5;
    const int warpM = wid & 3;      // 4 warps over M (32 rows each)
    const int warpN = wid >> 2;     // 2 warps over N (64 cols each)
    const int tile  = blockIdx.x * 128;

    float acc[2][8][4];
#pragma unroll
    for (int i = 0; i < 2; i++)
#pragma unroll
        for (int j = 0; j < 8; j++)
#pragma unroll
            for (int q = 0; q < 4; q++) acc[i][j][q] = 0.f;

    const int KT = K >> 5;

    // lane decomposition for ldmatrix address generation
    const int aRowIn = (lane & 7) + ((lane >> 3) & 1) * 8;
    const int aHi    = (lane >> 4) & 1;
    const int bRowIn = (lane & 7) + ((lane >> 4) & 1) * 8;
    const int bHi    = (lane >> 3) & 1;

    // R1 fill geometry: 8 consecutive lanes cover one contiguous 128B row chunk
    auto fill = [&](int kt) {
        float* st = sm + (kt % STAGES) * STAGE_FLOATS;
        int kg = kt << 5;
#pragma unroll
        for (int i = 0; i < 4; ++i) {
            int idx = tid + i * 256;
            int r   = idx >> 3;          // 0..127
            int cc  = idx & 7;           // 16B chunk within 128B row
            int row = tile + r;
            if (row >= nrows) row = nrows - 1;   // clamp (stores are guarded)
            int k   = kg + cc * 4;
            int col = (k < blk) ? (offA0 + k) : (offA1 + (k - blk));
            const float* srcA = A + (long)row * lda + col;
            unsigned dA = smem_u32(st + r * 32 + 4 * (cc ^ (r & 7)));
            asm volatile("cp.async.cg.shared.global [%0], [%1], 16;" ::"r"(dA), "l"(srcA));
            const float* srcB = B + (long)r * ldb + k;
            unsigned dB = smem_u32(st + 4096 + r * 32 + 4 * (cc ^ (r & 7)));
            asm volatile("cp.async.cg.shared.global [%0], [%1], 16;" ::"r"(dB), "l"(srcB));
        }
        asm volatile("cp.async.commit_group;");
    };

    auto compute_stage = [&](int buf) {
        const float* As = sm + buf * STAGE_FLOATS;
        const float* Bs = As + 4096;
#pragma unroll
        for (int k8 = 0; k8 < 4; ++k8) {
            unsigned a[2][4];
#pragma unroll
            for (int mf = 0; mf < 2; ++mf) {
                int row   = warpM * 32 + mf * 16 + aRowIn;
                int chunk = ((k8 << 1) + aHi) ^ (row & 7);
                ldsm4(smem_u32(As + row * 32 + 4 * chunk),
                      a[mf][0], a[mf][1], a[mf][2], a[mf][3]);
            }
            unsigned b[8][2];
#pragma unroll
            for (int nq = 0; nq < 4; ++nq) {
                int nrow  = warpN * 64 + nq * 16 + bRowIn;
                int chunk = ((k8 << 1) + bHi) ^ (nrow & 7);
                unsigned r0, r1, r2, r3;
                ldsm4(smem_u32(Bs + nrow * 32 + 4 * chunk), r0, r1, r2, r3);
                b[nq * 2][0]     = r0;
                b[nq * 2][1]     = r1;
                b[nq * 2 + 1][0] = r2;
                b[nq * 2 + 1][1] = r3;
            }
#pragma unroll
            for (int mf = 0; mf < 2; ++mf)
#pragma unroll
                for (int nf = 0; nf < 8; ++nf)
                    mma_tf32(acc[mf][nf], a[mf], b[nf]);
        }
    };

    // prologue: 2-stage lookahead
    fill(0);
    fill(1);

    for (int kt = 0; kt < KT; ++kt) {
        if (kt + 2 < KT) {
            asm volatile("cp.async.wait_group 1;" ::: "memory");
        } else {
            asm volatile("cp.async.wait_group 0;" ::: "memory");
        }
        __syncthreads();                 // fill(kt) visible; all warps done with stage kt-1
        if (kt + 2 < KT) fill(kt + 2);   // overwrites stage (kt-1)%3 — safe after barrier
        compute_stage(kt % STAGES);
    }

    // Epilogue: bias + relu (+ tf32 rounding so the next layer's operand is exact)
    const int rbase = tile + warpM * 32 + (lane >> 2);
#pragma unroll
    for (int mf = 0; mf < 2; ++mf) {
        int r0 = rbase + mf * 16;
#pragma unroll
        for (int nf = 0; nf < 8; ++nf) {
            int col  = warpN * 64 + nf * 8 + (lane & 3) * 2;
            float b0 = __ldg(bias + col);
            float b1 = __ldg(bias + col + 1);
            float v0 = fmaxf(acc[mf][nf][0] + b0, 0.f);
            float v1 = fmaxf(acc[mf][nf][1] + b1, 0.f);
            float v2 = fmaxf(acc[mf][nf][2] + b0, 0.f);
            float v3 = fmaxf(acc[mf][nf][3] + b1, 0.f);
            if (ROUND_OUT) {
                v0 = tf32_round(v0); v1 = tf32_round(v1);
                v2 = tf32_round(v2); v3 = tf32_round(v3);
            }
            if (r0 < nrows)
                *reinterpret_cast<float2*>(C + (long)r0 * ldc + col) = make_float2(v0, v1);
            if (r0 + 8 < nrows)
                *reinterpret_cast<float2*>(C + (long)(r0 + 8) * ldc + col) = make_float2(v2, v3);
        }
    }
}

// ---------------- kernels ----------------

__global__ void prep_kernel(const float* __restrict__ w10, const float* __restrict__ w1,
                            const float* __restrict__ w2, const float* __restrict__ wf) {
    int i      = blockIdx.x * blockDim.x + threadIdx.x;
    int stride = gridDim.x * blockDim.x;
    for (int j = i; j < 128 * 1280; j += stride) g_W1_0[j] = tf32_round(w10[j]);
    for (int j = i; j < 6 * 128 * 512; j += stride) g_W1[j] = tf32_round(w1[j]);
    for (int j = i; j < 6 * 128 * 256; j += stride) g_W2[j] = tf32_round(w2[j]);
    for (int j = i; j < 256 * 768; j += stride) g_Wf[j] = tf32_round(wf[j]);
}

__global__ void __launch_bounds__(256, 2)
l1_kernel(const float* __restrict__ update, const float* __restrict__ b1_0,
          const float* __restrict__ b1, int nrows) {
    int g = blockIdx.y;
    if (g == 0) {
        // joints 0..4 are contiguous columns 0..1279 of the 4352-wide row
        gemm_core<true>(update, 4352, 0, 0, 1 << 20,
                        g_W1_0, 1280, b1_0, g_out1, 896, 1280, nrows);
    } else {
        gemm_core<true>(update, 4352, c_jA[g] * 256, c_jB[g] * 256, 256,
                        g_W1 + (g - 1) * 128 * 512, 512, b1 + (g - 1) * 128,
                        g_out1 + g * 128, 896, 512, nrows);
    }
}

__global__ void __launch_bounds__(256, 2)
l2_kernel(const float* __restrict__ b2, int nrows) {
    int g = blockIdx.y;
    gemm_core<true>(g_out1, 896, c_pA[g] * 128, c_pB[g] * 128, 128,
                    g_W2 + g * 128 * 256, 256, b2 + g * 128,
                    g_out2 + g * 128, 768, 256, nrows);
}

__global__ void __launch_bounds__(256, 2)
l3_kernel(const float* __restrict__ bf, float* __restrict__ out, int nrows) {
    int y = blockIdx.y;   // output column half (0: cols 0..127, 1: 128..255)
    gemm_core<false>(g_out2, 768, 0, 0, 1 << 20,
                     g_Wf + y * 128 * 768, 768, bf + y * 128,
                     out + y * 128, 256, 768, nrows);
}

// ---------------- launch ----------------

extern "C" void kernel_launch(void* const* d_in, const int* in_sizes, int n_in,
                              void* d_out, int out_size) {
    const float* update = (const float*)d_in[0];
    const float* W1_0   = (const float*)d_in[1];
    const float* b1_0   = (const float*)d_in[2];
    const float* W1     = (const float*)d_in[3];
    const float* b1     = (const float*)d_in[4];
    const float* W2     = (const float*)d_in[5];
    const float* b2     = (const float*)d_in[6];
    const float* Wf     = (const float*)d_in[7];
    const float* bf     = (const float*)d_in[8];

    int N  = in_sizes[0] / (17 * 256);
    int MT = (N + 127) / 128;

    cudaFuncSetAttribute(l1_kernel, cudaFuncAttributeMaxDynamicSharedMemorySize, SMEM_TOTAL);
    cudaFuncSetAttribute(l2_kernel, cudaFuncAttributeMaxDynamicSharedMemorySize, SMEM_TOTAL);
    cudaFuncSetAttribute(l3_kernel, cudaFuncAttributeMaxDynamicSharedMemorySize, SMEM_TOTAL);

    prep_kernel<<<232, 256>>>(W1_0, W1, W2, Wf);
    l1_kernel<<<dim3(MT, 7), 256, SMEM_TOTAL>>>(update, b1_0, b1, N);
    l2_kernel<<<dim3(MT, 6), 256, SMEM_TOTAL>>>(b2, N);
    l3_kernel<<<dim3(MT, 2), 256, SMEM_TOTAL>>>(bf, (float*)d_out, N);
}

// round 5
// speedup vs baseline: 1.9937x; 1.9937x over previous
#include <cuda_runtime.h>
#include <cuda_fp16.h>
#include <cstdint>

// ---------------------------------------------------------------------------
// HierarchUpdateMlp — fp16 mma.sync (m16n8k16), fp16 intermediates,
// R1's proven double-buffered cp.async loop.
//   L1:  out1[:,g] = relu(gather_g(update) @ W1g^T + b1g)   g=0..6
//   L2:  out2[:,g] = relu(gather_g(out1)   @ W2g^T + b2g)   g=0..5
//   L3:  out       = relu(out2 @ Wf^T + bf)
// ---------------------------------------------------------------------------

#define NROWS_MAX 50176   // 392 tiles of 128 (N = 50000)

__device__ __align__(16) __half g_W1_0h[128 * 1280];
__device__ __align__(16) __half g_W1h[6 * 128 * 512];
__device__ __align__(16) __half g_W2h[6 * 128 * 256];
__device__ __align__(16) __half g_Wfh[256 * 768];
__device__ __align__(16) __half g_out1h[(size_t)NROWS_MAX * 896];
__device__ __align__(16) __half g_out2h[(size_t)NROWS_MAX * 768];

__constant__ int c_jA[7] = {0, 5, 7, 8, 11, 13, 14};
__constant__ int c_jB[7] = {0, 6, 9, 10, 12, 15, 16};
__constant__ int c_pA[6] = {0, 1, 1, 1, 4, 4};
__constant__ int c_pB[6] = {1, 2, 3, 4, 5, 6};

// smem layout:
//   MODE1 (L1): [0,32768) fp32 A staging (2 x 128x32 f32)
//               [32768,49152) hA (2 x 128x32 half), [49152,65536) hB
//   MODE0:      [0,16384) hA, [16384,32768) hB
#define SMEM_L1 65536
#define SMEM_L23 32768

__device__ __forceinline__ unsigned smem_u32(const void* p) {
    return (unsigned)__cvta_generic_to_shared(p);
}

__device__ __forceinline__ void ldsm4(unsigned addr, unsigned& r0, unsigned& r1,
                                      unsigned& r2, unsigned& r3) {
    asm volatile("ldmatrix.sync.aligned.m8n8.x4.shared.b16 {%0,%1,%2,%3}, [%4];"
                 : "=r"(r0), "=r"(r1), "=r"(r2), "=r"(r3)
                 : "r"(addr));
}

__device__ __forceinline__ void mma_f16(float* c, const unsigned* a, const unsigned* b) {
    asm volatile(
        "mma.sync.aligned.m16n8k16.row.col.f32.f16.f16.f32 "
        "{%0,%1,%2,%3}, {%4,%5,%6,%7}, {%8,%9}, {%0,%1,%2,%3};"
        : "+f"(c[0]), "+f"(c[1]), "+f"(c[2]), "+f"(c[3])
        : "r"(a[0]), "r"(a[1]), "r"(a[2]), "r"(a[3]), "r"(b[0]), "r"(b[1]));
}

// fp16 smem tile: 128 rows x 32 halfs (64B/row), 16B chunks j=0..3,
// swizzle: chunk_eff = j ^ ((row>>1)&3)  -> conflict-free ldmatrix & fills.
// Generic 128(M)x128(N) GEMM, K streamed in 32-col stages, double-buffered.
// A gathered from up to 2 contiguous col blocks (col = k<blk ? offA0+k : offA1+k-blk).
// MODE==1: A is fp32 (L1 update), staged fp32 then converted to hA in smem.
// MODE==0: A is fp16 already.
template <int MODE, bool HALF_OUT>
__device__ __forceinline__ void gemm16(
    const void* __restrict__ Av, int lda, int offA0, int offA1, int blk,
    const __half* __restrict__ B, int ldb,
    const float* __restrict__ bias,
    void* __restrict__ Cv, int ldc,
    int K, int nrows)
{
    extern __shared__ char smc[];
    float*  f32A = reinterpret_cast<float*>(smc);
    __half* hA   = reinterpret_cast<__half*>(smc + (MODE ? 32768 : 0));
    __half* hB   = hA + 8192;

    const int tid   = threadIdx.x;
    const int lane  = tid & 31;
    const int wid   = tid >> 5;
    const int warpM = wid & 3;      // 4 warps over M (32 rows)
    const int warpN = wid >> 2;     // 2 warps over N (64 cols)
    const int tile  = blockIdx.x * 128;
    const int KT    = K >> 5;

    float acc[2][8][4];
#pragma unroll
    for (int i = 0; i < 2; i++)
#pragma unroll
        for (int j = 0; j < 8; j++)
#pragma unroll
            for (int q = 0; q < 4; q++) acc[i][j][q] = 0.f;

    const int rowIn = (lane & 7) + ((lane >> 3) & 1) * 8;
    const int hi    = (lane >> 4) & 1;

    auto fill = [&](int kt) {
        const int kg  = kt << 5;
        const int buf = kt & 1;
        if (MODE == 1) {
            // fp32 A staging: R1 geometry (8 lanes cover one contiguous 128B row chunk)
            float* fs = f32A + buf * 4096;
#pragma unroll
            for (int i = 0; i < 4; ++i) {
                int idx = tid + i * 256;
                int r   = idx >> 3;
                int cc  = idx & 7;
                int row = tile + r;
                if (row >= nrows) row = nrows - 1;
                int k   = kg + cc * 4;
                int col = (k < blk) ? (offA0 + k) : (offA1 + (k - blk));
                const float* src = (const float*)Av + (long)row * lda + col;
                unsigned dst = smem_u32(fs + r * 32 + 4 * (cc ^ (r & 7)));
                asm volatile("cp.async.cg.shared.global [%0], [%1], 16;"
                             ::"r"(dst), "l"(src));
            }
        } else {
            // fp16 A: 4 lanes per row (16B granules), 512 granules
            __half* hs = hA + buf * 4096;
#pragma unroll
            for (int i = 0; i < 2; ++i) {
                int idx = tid + i * 256;
                int r   = idx >> 2;
                int j   = idx & 3;
                int row = tile + r;
                if (row >= nrows) row = nrows - 1;
                int k   = kg + j * 8;
                int col = (k < blk) ? (offA0 + k) : (offA1 + (k - blk));
                const __half* src = (const __half*)Av + (long)row * lda + col;
                unsigned dst = smem_u32(hs + r * 32 + 8 * (j ^ ((r >> 1) & 3)));
                asm volatile("cp.async.cg.shared.global [%0], [%1], 16;"
                             ::"r"(dst), "l"(src));
            }
        }
        {
            __half* hs = hB + buf * 4096;
#pragma unroll
            for (int i = 0; i < 2; ++i) {
                int idx = tid + i * 256;
                int r   = idx >> 2;
                int j   = idx & 3;
                const __half* src = B + (long)r * ldb + kg + j * 8;
                unsigned dst = smem_u32(hs + r * 32 + 8 * (j ^ ((r >> 1) & 3)));
                asm volatile("cp.async.cg.shared.global [%0], [%1], 16;"
                             ::"r"(dst), "l"(src));
            }
        }
        asm volatile("cp.async.commit_group;");
    };

    auto convertA = [&](int kt) {
        const int buf   = kt & 1;
        const float* fs = f32A + buf * 4096;
        __half* hs      = hA + buf * 4096;
#pragma unroll
        for (int i = 0; i < 2; ++i) {
            int idx = tid + i * 256;
            int r   = idx >> 2;
            int j   = idx & 3;
            float4 v0 = *reinterpret_cast<const float4*>(fs + r * 32 + 4 * ((2 * j) ^ (r & 7)));
            float4 v1 = *reinterpret_cast<const float4*>(fs + r * 32 + 4 * ((2 * j + 1) ^ (r & 7)));
            __half2 h0 = __floats2half2_rn(v0.x, v0.y);
            __half2 h1 = __floats2half2_rn(v0.z, v0.w);
            __half2 h2 = __floats2half2_rn(v1.x, v1.y);
            __half2 h3 = __floats2half2_rn(v1.z, v1.w);
            uint4 u;
            u.x = *reinterpret_cast<unsigned*>(&h0);
            u.y = *reinterpret_cast<unsigned*>(&h1);
            u.z = *reinterpret_cast<unsigned*>(&h2);
            u.w = *reinterpret_cast<unsigned*>(&h3);
            *reinterpret_cast<uint4*>(hs + r * 32 + 8 * (j ^ ((r >> 1) & 3))) = u;
        }
    };

    auto compute_stage = [&](int buf) {
        const __half* As = hA + buf * 4096;
        const __half* Bs = hB + buf * 4096;
#pragma unroll
        for (int s = 0; s < 2; ++s) {         // two k16 steps per 32-K stage
            unsigned a[2][4];
#pragma unroll
            for (int mf = 0; mf < 2; ++mf) {
                int row = warpM * 32 + mf * 16 + rowIn;
                int j   = s * 2 + hi;
                ldsm4(smem_u32(As + row * 32 + 8 * (j ^ ((row >> 1) & 3))),
                      a[mf][0], a[mf][1], a[mf][2], a[mf][3]);
            }
            unsigned b[8][2];
#pragma unroll
            for (int nq = 0; nq < 4; ++nq) {
                int nrow = warpN * 64 + nq * 16 + rowIn;
                int j    = s * 2 + hi;
                unsigned r0, r1, r2, r3;
                ldsm4(smem_u32(Bs + nrow * 32 + 8 * (j ^ ((nrow >> 1) & 3))),
                      r0, r1, r2, r3);
                b[nq * 2][0]     = r0;   // n8#0 k0-7
                b[nq * 2 + 1][0] = r1;   // n8#1 k0-7
                b[nq * 2][1]     = r2;   // n8#0 k8-15
                b[nq * 2 + 1][1] = r3;   // n8#1 k8-15
            }
#pragma unroll
            for (int mf = 0; mf < 2; ++mf)
#pragma unroll
                for (int nf = 0; nf < 8; ++nf)
                    mma_f16(acc[mf][nf], a[mf], b[nf]);
        }
    };

    fill(0);
    for (int kt = 0; kt < KT; ++kt) {
        if (kt + 1 < KT) {
            fill(kt + 1);
            asm volatile("cp.async.wait_group 1;" ::: "memory");
        } else {
            asm volatile("cp.async.wait_group 0;" ::: "memory");
        }
        __syncthreads();
        if (MODE == 1) {
            convertA(kt);
            __syncthreads();
        }
        compute_stage(kt & 1);
        __syncthreads();
    }

    // Epilogue: bias + relu; store fp16 (intermediates) or fp32 (final)
    const int rbase = tile + warpM * 32 + (lane >> 2);
#pragma unroll
    for (int mf = 0; mf < 2; ++mf) {
        int r0 = rbase + mf * 16;
#pragma unroll
        for (int nf = 0; nf < 8; ++nf) {
            int col  = warpN * 64 + nf * 8 + (lane & 3) * 2;
            float b0 = __ldg(bias + col);
            float b1 = __ldg(bias + col + 1);
            float v0 = fmaxf(acc[mf][nf][0] + b0, 0.f);
            float v1 = fmaxf(acc[mf][nf][1] + b1, 0.f);
            float v2 = fmaxf(acc[mf][nf][2] + b0, 0.f);
            float v3 = fmaxf(acc[mf][nf][3] + b1, 0.f);
            if (HALF_OUT) {
                __half* Ch = (__half*)Cv;
                if (r0 < nrows)
                    *reinterpret_cast<__half2*>(Ch + (long)r0 * ldc + col) =
                        __floats2half2_rn(v0, v1);
                if (r0 + 8 < nrows)
                    *reinterpret_cast<__half2*>(Ch + (long)(r0 + 8) * ldc + col) =
                        __floats2half2_rn(v2, v3);
            } else {
                float* Cf = (float*)Cv;
                if (r0 < nrows)
                    *reinterpret_cast<float2*>(Cf + (long)r0 * ldc + col) =
                        make_float2(v0, v1);
                if (r0 + 8 < nrows)
                    *reinterpret_cast<float2*>(Cf + (long)(r0 + 8) * ldc + col) =
                        make_float2(v2, v3);
            }
        }
    }
}

// ---------------- kernels ----------------

__global__ void prep_kernel(const float* __restrict__ w10, const float* __restrict__ w1,
                            const float* __restrict__ w2, const float* __restrict__ wf) {
    int i      = blockIdx.x * blockDim.x + threadIdx.x;
    int stride = gridDim.x * blockDim.x;
    for (int j = i; j < 128 * 1280; j += stride) g_W1_0h[j] = __float2half_rn(w10[j]);
    for (int j = i; j < 6 * 128 * 512; j += stride) g_W1h[j] = __float2half_rn(w1[j]);
    for (int j = i; j < 6 * 128 * 256; j += stride) g_W2h[j] = __float2half_rn(w2[j]);
    for (int j = i; j < 256 * 768; j += stride) g_Wfh[j] = __float2half_rn(wf[j]);
}

__global__ void __launch_bounds__(256, 2)
l1_kernel(const float* __restrict__ update, const float* __restrict__ b1_0,
          const float* __restrict__ b1, int nrows) {
    int g = blockIdx.y;
    if (g == 0) {
        gemm16<1, true>(update, 4352, 0, 0, 1 << 20,
                        g_W1_0h, 1280, b1_0, g_out1h, 896, 1280, nrows);
    } else {
        gemm16<1, true>(update, 4352, c_jA[g] * 256, c_jB[g] * 256, 256,
                        g_W1h + (g - 1) * 128 * 512, 512, b1 + (g - 1) * 128,
                        g_out1h + g * 128, 896, 512, nrows);
    }
}

__global__ void __launch_bounds__(256, 2)
l2_kernel(const float* __restrict__ b2, int nrows) {
    int g = blockIdx.y;
    gemm16<0, true>(g_out1h, 896, c_pA[g] * 128, c_pB[g] * 128, 128,
                    g_W2h + g * 128 * 256, 256, b2 + g * 128,
                    g_out2h + g * 128, 768, 256, nrows);
}

__global__ void __launch_bounds__(256, 2)
l3_kernel(const float* __restrict__ bf, float* __restrict__ out, int nrows) {
    int y = blockIdx.y;   // output column half
    gemm16<0, false>(g_out2h, 768, 0, 0, 1 << 20,
                     g_Wfh + y * 128 * 768, 768, bf + y * 128,
                     out + y * 128, 256, 768, nrows);
}

// ---------------- launch ----------------

extern "C" void kernel_launch(void* const* d_in, const int* in_sizes, int n_in,
                              void* d_out, int out_size) {
    const float* update = (const float*)d_in[0];
    const float* W1_0   = (const float*)d_in[1];
    const float* b1_0   = (const float*)d_in[2];
    const float* W1     = (const float*)d_in[3];
    const float* b1     = (const float*)d_in[4];
    const float* W2     = (const float*)d_in[5];
    const float* b2     = (const float*)d_in[6];
    const float* Wf     = (const float*)d_in[7];
    const float* bf     = (const float*)d_in[8];

    int N  = in_sizes[0] / (17 * 256);
    int MT = (N + 127) / 128;

    cudaFuncSetAttribute(l1_kernel, cudaFuncAttributeMaxDynamicSharedMemorySize, SMEM_L1);
    cudaFuncSetAttribute(l2_kernel, cudaFuncAttributeMaxDynamicSharedMemorySize, SMEM_L23);
    cudaFuncSetAttribute(l3_kernel, cudaFuncAttributeMaxDynamicSharedMemorySize, SMEM_L23);

    prep_kernel<<<232, 256>>>(W1_0, W1, W2, Wf);
    l1_kernel<<<dim3(MT, 7), 256, SMEM_L1>>>(update, b1_0, b1, N);
    l2_kernel<<<dim3(MT, 6), 256, SMEM_L23>>>(b2, N);
    l3_kernel<<<dim3(MT, 2), 256, SMEM_L23>>>(bf, (float*)d_out, N);
}

// round 6
// speedup vs baseline: 2.0980x; 1.0523x over previous
#include <cuda_runtime.h>
#include <cuda_fp16.h>
#include <cstdint>

// ---------------------------------------------------------------------------
// HierarchUpdateMlp — fp16 mma.sync (m16n8k16), K-stage 64, fp16 intermediates
//   L1:  out1[:,g] = relu(gather_g(update) @ W1g^T + b1g)   g=0..6
//   L2:  out2[:,g] = relu(gather_g(out1)   @ W2g^T + b2g)   g=0..5
//   L3:  out       = relu(out2 @ Wf^T + bf)
// fp16 smem tiles: 128 rows x 64 halfs (128B rows), chunk pos = j ^ (row&7).
// ---------------------------------------------------------------------------

#define NROWS_MAX 50176   // 392 tiles of 128 (N = 50000)

__device__ __align__(16) __half g_W1_0h[128 * 1280];
__device__ __align__(16) __half g_W1h[6 * 128 * 512];
__device__ __align__(16) __half g_W2h[6 * 128 * 256];
__device__ __align__(16) __half g_Wfh[256 * 768];
__device__ __align__(16) __half g_out1h[(size_t)NROWS_MAX * 896];
__device__ __align__(16) __half g_out2h[(size_t)NROWS_MAX * 768];

__constant__ int c_jA[7] = {0, 5, 7, 8, 11, 13, 14};
__constant__ int c_jB[7] = {0, 6, 9, 10, 12, 15, 16};
__constant__ int c_pA[6] = {0, 1, 1, 1, 4, 4};
__constant__ int c_pB[6] = {1, 2, 3, 4, 5, 6};

// smem (bytes):
//  MODE1 (l1): [0,32768) fp32 staging (128x64 f32, single buffer)
//              [32768, 65536) hA x2 bufs, [65536, 98304) hB x2 bufs
//  MODE0:      [0,32768) hA x2, [32768,65536) hB x2
#define SMEM_L1 98304
#define SMEM_L23 65536

__device__ __forceinline__ unsigned smem_u32(const void* p) {
    return (unsigned)__cvta_generic_to_shared(p);
}

__device__ __forceinline__ void ldsm4(unsigned addr, unsigned& r0, unsigned& r1,
                                      unsigned& r2, unsigned& r3) {
    asm volatile("ldmatrix.sync.aligned.m8n8.x4.shared.b16 {%0,%1,%2,%3}, [%4];"
                 : "=r"(r0), "=r"(r1), "=r"(r2), "=r"(r3)
                 : "r"(addr));
}

__device__ __forceinline__ void mma_f16(float* c, const unsigned* a, const unsigned* b) {
    asm volatile(
        "mma.sync.aligned.m16n8k16.row.col.f32.f16.f16.f32 "
        "{%0,%1,%2,%3}, {%4,%5,%6,%7}, {%8,%9}, {%0,%1,%2,%3};"
        : "+f"(c[0]), "+f"(c[1]), "+f"(c[2]), "+f"(c[3])
        : "r"(a[0]), "r"(a[1]), "r"(a[2]), "r"(a[3]), "r"(b[0]), "r"(b[1]));
}

// Generic 128(M)x128(N) GEMM, K streamed in 64-col stages.
// A gathered from up to 2 contiguous col blocks (col = k<blk ? offA0+k : offA1+k-blk).
// MODE==1: A fp32 (update) via single-buffered fp32 staging + smem convert.
// MODE==0: A fp16.
template <int MODE, bool HALF_OUT>
__device__ __forceinline__ void gemm16(
    const void* __restrict__ Av, int lda, int offA0, int offA1, int blk,
    const __half* __restrict__ B, int ldb,
    const float* __restrict__ bias,
    void* __restrict__ Cv, int ldc,
    int K, int nrows)
{
    extern __shared__ char smc[];
    float*  f32A = reinterpret_cast<float*>(smc);                       // MODE1 only
    __half* hA   = reinterpret_cast<__half*>(smc + (MODE ? 32768 : 0)); // 2 bufs x 8192 halfs
    __half* hB   = hA + 16384;                                          // 2 bufs x 8192 halfs

    const int tid   = threadIdx.x;
    const int lane  = tid & 31;
    const int wid   = tid >> 5;
    const int warpM = wid & 3;      // 4 warps over M (32 rows)
    const int warpN = wid >> 2;     // 2 warps over N (64 cols)
    const int tile  = blockIdx.x * 128;
    const int KT    = K >> 6;       // 64-K stages

    float acc[2][8][4];
#pragma unroll
    for (int i = 0; i < 2; i++)
#pragma unroll
        for (int j = 0; j < 8; j++)
#pragma unroll
            for (int q = 0; q < 4; q++) acc[i][j][q] = 0.f;

    const int rowIn = (lane & 7) + ((lane >> 3) & 1) * 8;
    const int hi    = (lane >> 4) & 1;

    // ---- B fill: 1024 granules of 16B (128 rows x 8 chunks) ----
    auto fillB = [&](int kt) {
        __half* hs = hB + (kt & 1) * 8192;
        const int kg = kt << 6;
#pragma unroll
        for (int i = 0; i < 4; ++i) {
            int idx = tid + i * 256;
            int r   = idx >> 3;
            int j   = idx & 7;
            const __half* src = B + (long)r * ldb + kg + j * 8;
            unsigned dst = smem_u32(hs + r * 64 + 8 * (j ^ (r & 7)));
            asm volatile("cp.async.cg.shared.global [%0], [%1], 16;"
                         ::"r"(dst), "l"(src));
        }
    };

    // ---- A fill MODE0 (fp16): same geometry as B, with gather ----
    auto fillA0 = [&](int kt) {
        __half* hs = hA + (kt & 1) * 8192;
        const int kg = kt << 6;
#pragma unroll
        for (int i = 0; i < 4; ++i) {
            int idx = tid + i * 256;
            int r   = idx >> 3;
            int j   = idx & 7;
            int row = tile + r;
            if (row >= nrows) row = nrows - 1;
            int k   = kg + j * 8;
            int col = (k < blk) ? (offA0 + k) : (offA1 + (k - blk));
            const __half* src = (const __half*)Av + (long)row * lda + col;
            unsigned dst = smem_u32(hs + r * 64 + 8 * (j ^ (r & 7)));
            asm volatile("cp.async.cg.shared.global [%0], [%1], 16;"
                         ::"r"(dst), "l"(src));
        }
    };

    // ---- A fill MODE1 (fp32 -> staging): 2048 granules (128 rows x 16 chunks) ----
    auto fillA1 = [&](int kt) {
        const int kg = kt << 6;
#pragma unroll
        for (int i = 0; i < 8; ++i) {
            int idx = tid + i * 256;
            int r   = idx >> 4;
            int cc  = idx & 15;
            int row = tile + r;
            if (row >= nrows) row = nrows - 1;
            int k   = kg + cc * 4;
            int col = (k < blk) ? (offA0 + k) : (offA1 + (k - blk));
            const float* src = (const float*)Av + (long)row * lda + col;
            unsigned dst = smem_u32(f32A + r * 64 + 4 * ((cc & 8) | ((cc & 7) ^ (r & 7))));
            asm volatile("cp.async.cg.shared.global [%0], [%1], 16;"
                         ::"r"(dst), "l"(src));
        }
    };

    // ---- staging -> hA[buf] fp16 convert (thread: row tid>>1, half tid&1) ----
    auto convertA = [&](int buf) {
        __half* hs  = hA + buf * 8192;
        const int r = tid >> 1;
        const int h = tid & 1;
        const int rx = r & 7;
        const float* fr = f32A + r * 64 + h * 32;   // base before swizzle (chunk math below)
        (void)fr;
#pragma unroll
        for (int q = 0; q < 4; ++q) {
            float4 va = *reinterpret_cast<const float4*>(
                f32A + r * 64 + 4 * (h * 8 + ((2 * q) ^ rx)));
            float4 vb = *reinterpret_cast<const float4*>(
                f32A + r * 64 + 4 * (h * 8 + ((2 * q + 1) ^ rx)));
            __half2 h0 = __floats2half2_rn(va.x, va.y);
            __half2 h1 = __floats2half2_rn(va.z, va.w);
            __half2 h2 = __floats2half2_rn(vb.x, vb.y);
            __half2 h3 = __floats2half2_rn(vb.z, vb.w);
            uint4 u;
            u.x = *reinterpret_cast<unsigned*>(&h0);
            u.y = *reinterpret_cast<unsigned*>(&h1);
            u.z = *reinterpret_cast<unsigned*>(&h2);
            u.w = *reinterpret_cast<unsigned*>(&h3);
            *reinterpret_cast<uint4*>(hs + r * 64 + 8 * ((h * 4 + q) ^ rx)) = u;
        }
    };

    auto compute_stage = [&](int buf) {
        const __half* As = hA + buf * 8192;
        const __half* Bs = hB + buf * 8192;
#pragma unroll
        for (int s = 0; s < 4; ++s) {         // four k16 steps per 64-K stage
            const int j = 2 * s + hi;
            unsigned a[2][4];
#pragma unroll
            for (int mf = 0; mf < 2; ++mf) {
                int row = warpM * 32 + mf * 16 + rowIn;
                ldsm4(smem_u32(As + row * 64 + 8 * (j ^ (row & 7))),
                      a[mf][0], a[mf][1], a[mf][2], a[mf][3]);
            }
            unsigned b[8][2];
#pragma unroll
            for (int nq = 0; nq < 4; ++nq) {
                int nrow = warpN * 64 + nq * 16 + rowIn;
                unsigned r0, r1, r2, r3;
                ldsm4(smem_u32(Bs + nrow * 64 + 8 * (j ^ (nrow & 7))),
                      r0, r1, r2, r3);
                b[nq * 2][0]     = r0;
                b[nq * 2 + 1][0] = r1;
                b[nq * 2][1]     = r2;
                b[nq * 2 + 1][1] = r3;
            }
#pragma unroll
            for (int mf = 0; mf < 2; ++mf)
#pragma unroll
                for (int nf = 0; nf < 8; ++nf)
                    mma_f16(acc[mf][nf], a[mf], b[nf]);
        }
    };

    if (MODE == 1) {
        // single-buffered staging; 2 syncs per 64-K stage
        fillA1(0); fillB(0);
        asm volatile("cp.async.commit_group;");
        for (int kt = 0; kt < KT; ++kt) {
            asm volatile("cp.async.wait_group 0;" ::: "memory");
            __syncthreads();                    // cp data visible; compute(kt-1) done
            convertA(kt & 1);                   // staging -> hA[kt&1]
            __syncthreads();                    // converts done; staging free
            if (kt + 1 < KT) {
                fillA1(kt + 1); fillB(kt + 1);
                asm volatile("cp.async.commit_group;");
            }
            compute_stage(kt & 1);
        }
    } else {
        fillA0(0); fillB(0);
        asm volatile("cp.async.commit_group;");
        for (int kt = 0; kt < KT; ++kt) {
            if (kt + 1 < KT) {
                fillA0(kt + 1); fillB(kt + 1);
                asm volatile("cp.async.commit_group;");
                asm volatile("cp.async.wait_group 1;" ::: "memory");
            } else {
                asm volatile("cp.async.wait_group 0;" ::: "memory");
            }
            __syncthreads();
            compute_stage(kt & 1);
            __syncthreads();
        }
    }

    // Epilogue: bias + relu; store fp16 (intermediates) or fp32 (final)
    const int rbase = tile + warpM * 32 + (lane >> 2);
#pragma unroll
    for (int mf = 0; mf < 2; ++mf) {
        int r0 = rbase + mf * 16;
#pragma unroll
        for (int nf = 0; nf < 8; ++nf) {
            int col  = warpN * 64 + nf * 8 + (lane & 3) * 2;
            float b0 = __ldg(bias + col);
            float b1 = __ldg(bias + col + 1);
            float v0 = fmaxf(acc[mf][nf][0] + b0, 0.f);
            float v1 = fmaxf(acc[mf][nf][1] + b1, 0.f);
            float v2 = fmaxf(acc[mf][nf][2] + b0, 0.f);
            float v3 = fmaxf(acc[mf][nf][3] + b1, 0.f);
            if (HALF_OUT) {
                __half* Ch = (__half*)Cv;
                if (r0 < nrows)
                    *reinterpret_cast<__half2*>(Ch + (long)r0 * ldc + col) =
                        __floats2half2_rn(v0, v1);
                if (r0 + 8 < nrows)
                    *reinterpret_cast<__half2*>(Ch + (long)(r0 + 8) * ldc + col) =
                        __floats2half2_rn(v2, v3);
            } else {
                float* Cf = (float*)Cv;
                if (r0 < nrows)
                    *reinterpret_cast<float2*>(Cf + (long)r0 * ldc + col) =
                        make_float2(v0, v1);
                if (r0 + 8 < nrows)
                    *reinterpret_cast<float2*>(Cf + (long)(r0 + 8) * ldc + col) =
                        make_float2(v2, v3);
            }
        }
    }
}

// ---------------- kernels ----------------

__global__ void prep_kernel(const float* __restrict__ w10, const float* __restrict__ w1,
                            const float* __restrict__ w2, const float* __restrict__ wf) {
    int i      = blockIdx.x * blockDim.x + threadIdx.x;
    int stride = gridDim.x * blockDim.x;
    for (int j = i; j < 128 * 1280; j += stride) g_W1_0h[j] = __float2half_rn(w10[j]);
    for (int j = i; j < 6 * 128 * 512; j += stride) g_W1h[j] = __float2half_rn(w1[j]);
    for (int j = i; j < 6 * 128 * 256; j += stride) g_W2h[j] = __float2half_rn(w2[j]);
    for (int j = i; j < 256 * 768; j += stride) g_Wfh[j] = __float2half_rn(wf[j]);
}

__global__ void __launch_bounds__(256, 2)
l1_kernel(const float* __restrict__ update, const float* __restrict__ b1_0,
          const float* __restrict__ b1, int nrows) {
    int g = blockIdx.y;
    if (g == 0) {
        gemm16<1, true>(update, 4352, 0, 0, 1 << 20,
                        g_W1_0h, 1280, b1_0, g_out1h, 896, 1280, nrows);
    } else {
        gemm16<1, true>(update, 4352, c_jA[g] * 256, c_jB[g] * 256, 256,
                        g_W1h + (g - 1) * 128 * 512, 512, b1 + (g - 1) * 128,
                        g_out1h + g * 128, 896, 512, nrows);
    }
}

__global__ void __launch_bounds__(256, 2)
l2_kernel(const float* __restrict__ b2, int nrows) {
    int g = blockIdx.y;
    gemm16<0, true>(g_out1h, 896, c_pA[g] * 128, c_pB[g] * 128, 128,
                    g_W2h + g * 128 * 256, 256, b2 + g * 128,
                    g_out2h + g * 128, 768, 256, nrows);
}

__global__ void __launch_bounds__(256, 2)
l3_kernel(const float* __restrict__ bf, float* __restrict__ out, int nrows) {
    int y = blockIdx.y;   // output column half
    gemm16<0, false>(g_out2h, 768, 0, 0, 1 << 20,
                     g_Wfh + y * 128 * 768, 768, bf + y * 128,
                     out + y * 128, 256, 768, nrows);
}

// ---------------- launch ----------------

extern "C" void kernel_launch(void* const* d_in, const int* in_sizes, int n_in,
                              void* d_out, int out_size) {
    const float* update = (const float*)d_in[0];
    const float* W1_0   = (const float*)d_in[1];
    const float* b1_0   = (const float*)d_in[2];
    const float* W1     = (const float*)d_in[3];
    const float* b1     = (const float*)d_in[4];
    const float* W2     = (const float*)d_in[5];
    const float* b2     = (const float*)d_in[6];
    const float* Wf     = (const float*)d_in[7];
    const float* bf     = (const float*)d_in[8];

    int N  = in_sizes[0] / (17 * 256);
    int MT = (N + 127) / 128;

    cudaFuncSetAttribute(l1_kernel, cudaFuncAttributeMaxDynamicSharedMemorySize, SMEM_L1);
    cudaFuncSetAttribute(l2_kernel, cudaFuncAttributeMaxDynamicSharedMemorySize, SMEM_L23);
    cudaFuncSetAttribute(l3_kernel, cudaFuncAttributeMaxDynamicSharedMemorySize, SMEM_L23);

    prep_kernel<<<232, 256>>>(W1_0, W1, W2, Wf);
    l1_kernel<<<dim3(MT, 7), 256, SMEM_L1>>>(update, b1_0, b1, N);
    l2_kernel<<<dim3(MT, 6), 256, SMEM_L23>>>(b2, N);
    l3_kernel<<<dim3(MT, 2), 256, SMEM_L23>>>(bf, (float*)d_out, N);
}

// round 7
// speedup vs baseline: 2.1010x; 1.0014x over previous
#include <cuda_runtime.h>
#include <cuda_fp16.h>
#include <cstdint>

// ---------------------------------------------------------------------------
// HierarchUpdateMlp — fp16 mma.sync (m16n8k16), K-stage 64, templated K,
// strength-reduced fills, fp16 intermediates.
//   L1:  out1[:,g] = relu(gather_g(update) @ W1g^T + b1g)   g=0..6
//   L2:  out2[:,g] = relu(gather_g(out1)   @ W2g^T + b2g)   g=0..5
//   L3:  out       = relu(out2 @ Wf^T + bf)
// fp16 smem tiles: 128 rows x 64 halfs (128B rows), chunk pos = j ^ (row&7).
// ---------------------------------------------------------------------------

#define NROWS_MAX 50176   // 392 tiles of 128 (N = 50000)

__device__ __align__(16) __half g_W1_0h[128 * 1280];
__device__ __align__(16) __half g_W1h[6 * 128 * 512];
__device__ __align__(16) __half g_W2h[6 * 128 * 256];
__device__ __align__(16) __half g_Wfh[256 * 768];
__device__ __align__(16) __half g_out1h[(size_t)NROWS_MAX * 896];
__device__ __align__(16) __half g_out2h[(size_t)NROWS_MAX * 768];

__constant__ int c_jA[7] = {0, 5, 7, 8, 11, 13, 14};
__constant__ int c_jB[7] = {0, 6, 9, 10, 12, 15, 16};
__constant__ int c_pA[6] = {0, 1, 1, 1, 4, 4};
__constant__ int c_pB[6] = {1, 2, 3, 4, 5, 6};

// smem (bytes):
//  MODE1 (l1): [0,32768) fp32 staging (1 buf), [32768,49152) hA (1 buf),
//              [49152,81920) hB x2 bufs
//  MODE0:      [0,32768) hA x2, [32768,65536) hB x2
#define SMEM_L1 81920
#define SMEM_L23 65536

__device__ __forceinline__ unsigned smem_u32(const void* p) {
    return (unsigned)__cvta_generic_to_shared(p);
}

__device__ __forceinline__ void ldsm4(unsigned addr, unsigned& r0, unsigned& r1,
                                      unsigned& r2, unsigned& r3) {
    asm volatile("ldmatrix.sync.aligned.m8n8.x4.shared.b16 {%0,%1,%2,%3}, [%4];"
                 : "=r"(r0), "=r"(r1), "=r"(r2), "=r"(r3)
                 : "r"(addr));
}

__device__ __forceinline__ void mma_f16(float* c, const unsigned* a, const unsigned* b) {
    asm volatile(
        "mma.sync.aligned.m16n8k16.row.col.f32.f16.f16.f32 "
        "{%0,%1,%2,%3}, {%4,%5,%6,%7}, {%8,%9}, {%0,%1,%2,%3};"
        : "+f"(c[0]), "+f"(c[1]), "+f"(c[2]), "+f"(c[3])
        : "r"(a[0]), "r"(a[1]), "r"(a[2]), "r"(a[3]), "r"(b[0]), "r"(b[1]));
}

// Generic 128(M)x128(N) GEMM, K streamed in 64-col stages (K compile-time).
// A gathered from up to 2 contiguous col blocks (col = k<blk ? offA0+k : offA1+k-blk).
// MODE==1: A fp32 (update) via single-buffered fp32 staging + smem convert.
// MODE==0: A fp16.
template <int MODE, bool HALF_OUT, int K>
__device__ __forceinline__ void gemm16(
    const void* __restrict__ Av, int lda, int offA0, int offA1, int blk,
    const __half* __restrict__ B, int ldb,
    const float* __restrict__ bias,
    void* __restrict__ Cv, int ldc,
    int nrows)
{
    extern __shared__ char smc[];
    float*  f32A = reinterpret_cast<float*>(smc);                       // MODE1 only
    __half* hA   = reinterpret_cast<__half*>(smc + (MODE ? 32768 : 0));
    __half* hB   = hA + (MODE ? 8192 : 16384);

    const int tid   = threadIdx.x;
    const int lane  = tid & 31;
    const int wid   = tid >> 5;
    const int warpM = wid & 3;      // 4 warps over M (32 rows)
    const int warpN = wid >> 2;     // 2 warps over N (64 cols)
    const int tile  = blockIdx.x * 128;
    constexpr int KT = K >> 6;      // 64-K stages

    float acc[2][8][4];
#pragma unroll
    for (int i = 0; i < 2; i++)
#pragma unroll
        for (int j = 0; j < 8; j++)
#pragma unroll
            for (int q = 0; q < 4; q++) acc[i][j][q] = 0.f;

    const int rowIn = (lane & 7) + ((lane >> 3) & 1) * 8;
    const int hi    = (lane >> 4) & 1;

    // ---------- precomputed fill geometry (thread-fixed) ----------
    // B / A0 geometry: r = idx>>3, j = idx&7  (4 granules of 16B per thread)
    const int fr8  = tid >> 3;          // base row for i=0 (stride 32 rows per i)
    const int fj   = tid & 7;
    // MODE1 staging geometry: r = idx>>4, j16 = idx&15 (8 granules per thread)
    const int fr16 = tid >> 4;          // stride 16 rows per i
    const int fj16 = tid & 15;

    // B: thread-fixed source pointer (advance by 64 per stage)
    const __half* bSrc0 = B + (long)fr8 * ldb + fj * 8;
    // B smem dst offsets (bytes, thread-fixed) for i=0..3; add buf offset
    unsigned bDst[4];
#pragma unroll
    for (int i = 0; i < 4; ++i) {
        int r = fr8 + i * 32;
        bDst[i] = smem_u32(hB + r * 64 + 8 * (fj ^ (r & 7)));
    }

    auto fillB = [&](int kt) {
        const unsigned boff = (unsigned)((kt & 1) * 16384);   // bytes
        const __half* src = bSrc0 + (kt << 6);
#pragma unroll
        for (int i = 0; i < 4; ++i)
            asm volatile("cp.async.cg.shared.global [%0], [%1], 16;"
                         ::"r"(bDst[i] + boff), "l"(src + (long)i * 32 * ldb));
    };

    // A MODE0: source row pointers (row-clamped), gather select per stage
    const __half* a0Src[4];
    unsigned a0Dst[4];
    if (MODE == 0) {
#pragma unroll
        for (int i = 0; i < 4; ++i) {
            int r = fr8 + i * 32;
            int row = tile + r; if (row >= nrows) row = nrows - 1;
            a0Src[i] = (const __half*)Av + (long)row * lda;
            a0Dst[i] = smem_u32(hA + r * 64 + 8 * (fj ^ (r & 7)));
        }
    }
    auto fillA0 = [&](int kt) {
        const unsigned boff = (unsigned)((kt & 1) * 16384);
        int k   = (kt << 6) + fj * 8;
        int col = (k < blk) ? (offA0 + k) : (offA1 + (k - blk));
#pragma unroll
        for (int i = 0; i < 4; ++i)
            asm volatile("cp.async.cg.shared.global [%0], [%1], 16;"
                         ::"r"(a0Dst[i] + boff), "l"(a0Src[i] + col));
    };

    // A MODE1: fp32 staging (single buffer)
    const float* a1Src[8];
    unsigned a1Dst[8];
    if (MODE == 1) {
#pragma unroll
        for (int i = 0; i < 8; ++i) {
            int r = fr16 + i * 16;
            int row = tile + r; if (row >= nrows) row = nrows - 1;
            a1Src[i] = (const float*)Av + (long)row * lda;
            a1Dst[i] = smem_u32(f32A + r * 64 +
                                4 * ((fj16 & 8) | ((fj16 & 7) ^ (r & 7))));
        }
    }
    auto fillA1 = [&](int kt) {
        int k   = (kt << 6) + fj16 * 4;
        int col = (k < blk) ? (offA0 + k) : (offA1 + (k - blk));
#pragma unroll
        for (int i = 0; i < 8; ++i)
            asm volatile("cp.async.cg.shared.global [%0], [%1], 16;"
                         ::"r"(a1Dst[i]), "l"(a1Src[i] + col));
    };

    // staging -> hA fp16 convert (thread: row tid>>1, half tid&1)
    auto convertA = [&]() {
        const int r  = tid >> 1;
        const int h  = tid & 1;
        const int rx = r & 7;
#pragma unroll
        for (int q = 0; q < 4; ++q) {
            float4 va = *reinterpret_cast<const float4*>(
                f32A + r * 64 + 4 * (h * 8 + ((2 * q) ^ rx)));
            float4 vb = *reinterpret_cast<const float4*>(
                f32A + r * 64 + 4 * (h * 8 + ((2 * q + 1) ^ rx)));
            __half2 h0 = __floats2half2_rn(va.x, va.y);
            __half2 h1 = __floats2half2_rn(va.z, va.w);
            __half2 h2 = __floats2half2_rn(vb.x, vb.y);
            __half2 h3 = __floats2half2_rn(vb.z, vb.w);
            uint4 u;
            u.x = *reinterpret_cast<unsigned*>(&h0);
            u.y = *reinterpret_cast<unsigned*>(&h1);
            u.z = *reinterpret_cast<unsigned*>(&h2);
            u.w = *reinterpret_cast<unsigned*>(&h3);
            *reinterpret_cast<uint4*>(hA + r * 64 + 8 * ((h * 4 + q) ^ rx)) = u;
        }
    };

    // compute: MODE1 reads hA (single buf); MODE0 reads hA[buf]
    auto compute_stage = [&](int buf) {
        const __half* As = hA + (MODE ? 0 : buf * 8192);
        const __half* Bs = hB + buf * 8192;
#pragma unroll
        for (int s = 0; s < 4; ++s) {         // four k16 steps per 64-K stage
            const int j = 2 * s + hi;
            unsigned a[2][4];
#pragma unroll
            for (int mf = 0; mf < 2; ++mf) {
                int row = warpM * 32 + mf * 16 + rowIn;
                ldsm4(smem_u32(As + row * 64 + 8 * (j ^ (row & 7))),
                      a[mf][0], a[mf][1], a[mf][2], a[mf][3]);
            }
            unsigned b[8][2];
#pragma unroll
            for (int nq = 0; nq < 4; ++nq) {
                int nrow = warpN * 64 + nq * 16 + rowIn;
                unsigned r0, r1, r2, r3;
                ldsm4(smem_u32(Bs + nrow * 64 + 8 * (j ^ (nrow & 7))),
                      r0, r1, r2, r3);
                b[nq * 2][0]     = r0;
                b[nq * 2 + 1][0] = r1;
                b[nq * 2][1]     = r2;
                b[nq * 2 + 1][1] = r3;
            }
#pragma unroll
            for (int mf = 0; mf < 2; ++mf)
#pragma unroll
                for (int nf = 0; nf < 8; ++nf)
                    mma_f16(acc[mf][nf], a[mf], b[nf]);
        }
    };

    if (MODE == 1) {
        fillA1(0); fillB(0);
        asm volatile("cp.async.commit_group;");
#pragma unroll 4
        for (int kt = 0; kt < KT; ++kt) {
            asm volatile("cp.async.wait_group 0;" ::: "memory");
            __syncthreads();                    // cp data visible; compute(kt-1) done
            convertA();                         // staging -> hA
            __syncthreads();                    // converts done; staging free
            if (kt + 1 < KT) {
                fillA1(kt + 1); fillB(kt + 1);
                asm volatile("cp.async.commit_group;");
            }
            compute_stage(kt & 1);
        }
    } else {
        fillA0(0); fillB(0);
        asm volatile("cp.async.commit_group;");
#pragma unroll 4
        for (int kt = 0; kt < KT; ++kt) {
            if (kt + 1 < KT) {
                fillA0(kt + 1); fillB(kt + 1);
                asm volatile("cp.async.commit_group;");
                asm volatile("cp.async.wait_group 1;" ::: "memory");
            } else {
                asm volatile("cp.async.wait_group 0;" ::: "memory");
            }
            __syncthreads();
            compute_stage(kt & 1);
            __syncthreads();
        }
    }

    // Epilogue: bias + relu; store fp16 (intermediates) or fp32 (final)
    const int rbase = tile + warpM * 32 + (lane >> 2);
#pragma unroll
    for (int mf = 0; mf < 2; ++mf) {
        int r0 = rbase + mf * 16;
#pragma unroll
        for (int nf = 0; nf < 8; ++nf) {
            int col  = warpN * 64 + nf * 8 + (lane & 3) * 2;
            float b0 = __ldg(bias + col);
            float b1 = __ldg(bias + col + 1);
            float v0 = fmaxf(acc[mf][nf][0] + b0, 0.f);
            float v1 = fmaxf(acc[mf][nf][1] + b1, 0.f);
            float v2 = fmaxf(acc[mf][nf][2] + b0, 0.f);
            float v3 = fmaxf(acc[mf][nf][3] + b1, 0.f);
            if (HALF_OUT) {
                __half* Ch = (__half*)Cv;
                if (r0 < nrows)
                    *reinterpret_cast<__half2*>(Ch + (long)r0 * ldc + col) =
                        __floats2half2_rn(v0, v1);
                if (r0 + 8 < nrows)
                    *reinterpret_cast<__half2*>(Ch + (long)(r0 + 8) * ldc + col) =
                        __floats2half2_rn(v2, v3);
            } else {
                float* Cf = (float*)Cv;
                if (r0 < nrows)
                    *reinterpret_cast<float2*>(Cf + (long)r0 * ldc + col) =
                        make_float2(v0, v1);
                if (r0 + 8 < nrows)
                    *reinterpret_cast<float2*>(Cf + (long)(r0 + 8) * ldc + col) =
                        make_float2(v2, v3);
            }
        }
    }
}

// ---------------- kernels ----------------

__global__ void prep_kernel(const float* __restrict__ w10, const float* __restrict__ w1,
                            const float* __restrict__ w2, const float* __restrict__ wf) {
    int i      = blockIdx.x * blockDim.x + threadIdx.x;
    int stride = gridDim.x * blockDim.x;
    for (int j = i; j < 128 * 1280; j += stride) g_W1_0h[j] = __float2half_rn(w10[j]);
    for (int j = i; j < 6 * 128 * 512; j += stride) g_W1h[j] = __float2half_rn(w1[j]);
    for (int j = i; j < 6 * 128 * 256; j += stride) g_W2h[j] = __float2half_rn(w2[j]);
    for (int j = i; j < 256 * 768; j += stride) g_Wfh[j] = __float2half_rn(wf[j]);
}

__global__ void __launch_bounds__(256, 2)
l1_kernel(const float* __restrict__ update, const float* __restrict__ b1_0,
          const float* __restrict__ b1, int nrows) {
    int g = blockIdx.y;
    if (g == 0) {
        gemm16<1, true, 1280>(update, 4352, 0, 0, 1 << 20,
                              g_W1_0h, 1280, b1_0, g_out1h, 896, nrows);
    } else {
        gemm16<1, true, 512>(update, 4352, c_jA[g] * 256, c_jB[g] * 256, 256,
                             g_W1h + (g - 1) * 128 * 512, 512, b1 + (g - 1) * 128,
                             g_out1h + g * 128, 896, nrows);
    }
}

__global__ void __launch_bounds__(256, 2)
l2_kernel(const float* __restrict__ b2, int nrows) {
    int g = blockIdx.y;
    gemm16<0, true, 256>(g_out1h, 896, c_pA[g] * 128, c_pB[g] * 128, 128,
                         g_W2h + g * 128 * 256, 256, b2 + g * 128,
                         g_out2h + g * 128, 768, nrows);
}

__global__ void __launch_bounds__(256, 2)
l3_kernel(const float* __restrict__ bf, float* __restrict__ out, int nrows) {
    int y = blockIdx.y;   // output column half
    gemm16<0, false, 768>(g_out2h, 768, 0, 0, 1 << 20,
                          g_Wfh + y * 128 * 768, 768, bf + y * 128,
                          out + y * 128, 256, nrows);
}

// ---------------- launch ----------------

extern "C" void kernel_launch(void* const* d_in, const int* in_sizes, int n_in,
                              void* d_out, int out_size) {
    const float* update = (const float*)d_in[0];
    const float* W1_0   = (const float*)d_in[1];
    const float* b1_0   = (const float*)d_in[2];
    const float* W1     = (const float*)d_in[3];
    const float* b1     = (const float*)d_in[4];
    const float* W2     = (const float*)d_in[5];
    const float* b2     = (const float*)d_in[6];
    const float* Wf     = (const float*)d_in[7];
    const float* bf     = (const float*)d_in[8];

    int N  = in_sizes[0] / (17 * 256);
    int MT = (N + 127) / 128;

    cudaFuncSetAttribute(l1_kernel, cudaFuncAttributeMaxDynamicSharedMemorySize, SMEM_L1);
    cudaFuncSetAttribute(l2_kernel, cudaFuncAttributeMaxDynamicSharedMemorySize, SMEM_L23);
    cudaFuncSetAttribute(l3_kernel, cudaFuncAttributeMaxDynamicSharedMemorySize, SMEM_L23);

    prep_kernel<<<232, 256>>>(W1_0, W1, W2, Wf);
    l1_kernel<<<dim3(MT, 7), 256, SMEM_L1>>>(update, b1_0, b1, N);
    l2_kernel<<<dim3(MT, 6), 256, SMEM_L23>>>(b2, N);
    l3_kernel<<<dim3(MT, 2), 256, SMEM_L23>>>(bf, (float*)d_out, N);
}